// round 7
// baseline (speedup 1.0000x reference)
#include <cuda_runtime.h>
#include <cuda_fp16.h>
#include <math.h>
#include <stdint.h>

#define M_TOTAL 32768
#define E_DIM   512
#define F_DIM   2048

#define BM 128
#define BN 128
#define BK 32
#define THREADS 256
#define K_ITERS 64

// smem offsets (relative to 1024-aligned base)
#define SQ   0           // q fp32 [128][8] = 4096
#define SA0  4096        // A (H fp16) [128 rows][64B] dbl: 2 x 8192
#define SAB  8192
#define SB0  20480       // B (W2 fp16) [128 rows][64B] dbl: 2 x 8192
#define SBB  8192
#define SMEM_BYTES (36864 + 1024)

// fp16 copy of W2 (E x F), row-major [n][k], uint4 = 8 halves
__device__ uint4 g_W2h[E_DIM * F_DIM / 8];

__global__ void cvt_w2_kernel(const float* __restrict__ W2) {
    int i = blockIdx.x * 256 + threadIdx.x;
    float4 v = ((const float4*)W2)[i];
    __half2* o = (__half2*)g_W2h;
    o[2 * i]     = __floats2half2_rn(v.x, v.y);
    o[2 * i + 1] = __floats2half2_rn(v.z, v.w);
}

static __device__ __forceinline__ uint32_t cvta_smem(const void* p) {
    uint32_t a;
    asm("{ .reg .u64 t; cvta.to.shared.u64 t, %1; cvt.u32.u64 %0, t; }" : "=r"(a) : "l"(p));
    return a;
}

static __device__ __forceinline__ void sts128(uint32_t addr, uint32_t r0, uint32_t r1,
                                              uint32_t r2, uint32_t r3) {
    asm volatile("st.shared.v4.b32 [%0], {%1,%2,%3,%4};"
                 :: "r"(addr), "r"(r0), "r"(r1), "r"(r2), "r"(r3) : "memory");
}

static __device__ __forceinline__ void cpasync16(uint32_t dst, const void* src) {
    asm volatile("cp.async.ca.shared.global [%0], [%1], 16;"
                 :: "r"(dst), "l"(src) : "memory");
}

static __device__ __forceinline__ void ldsm4(uint32_t* r, uint32_t a) {
    asm volatile("ldmatrix.sync.aligned.m8n8.x4.shared.b16 {%0,%1,%2,%3}, [%4];"
                 : "=r"(r[0]), "=r"(r[1]), "=r"(r[2]), "=r"(r[3]) : "r"(a));
}

static __device__ __forceinline__ void mma_f16(float* c, const uint32_t* a,
                                               uint32_t b0, uint32_t b1) {
    asm volatile(
        "mma.sync.aligned.m16n8k16.row.col.f32.f16.f16.f32 "
        "{%0,%1,%2,%3},{%4,%5,%6,%7},{%8,%9},{%0,%1,%2,%3};"
        : "+f"(c[0]), "+f"(c[1]), "+f"(c[2]), "+f"(c[3])
        : "r"(a[0]), "r"(a[1]), "r"(a[2]), "r"(a[3]), "r"(b0), "r"(b1));
}

static __device__ __forceinline__ float dot8(const float4& qa, const float4& qb,
                                             const float4& wa, const float4& wb) {
    float t = qa.x * wa.x;
    t = fmaf(qa.y, wa.y, t);
    t = fmaf(qa.z, wa.z, t);
    t = fmaf(qa.w, wa.w, t);
    t = fmaf(qb.x, wb.x, t);
    t = fmaf(qb.y, wb.y, t);
    t = fmaf(qb.z, wb.z, t);
    t = fmaf(qb.w, wb.w, t);
    return t;
}

__global__ void __launch_bounds__(THREADS, 2)
ffq_kernel(const float* __restrict__ x,
           const float* __restrict__ theta,
           const float* __restrict__ W1,
           float* __restrict__ out)
{
    extern __shared__ char dsm[];
    const uint32_t raw = cvta_smem(dsm);
    const uint32_t sbase = (raw + 1023) & ~1023u;
    char* gb = dsm + (sbase - raw);

    const int tid  = threadIdx.x;
    const int warp = tid >> 5, lane = tid & 31;
    const int wm = warp >> 2, wn = warp & 3;       // consumer: 2 x 4 grid, warp tile 64x32
    const int mt = blockIdx.x >> 2, nt = blockIdx.x & 3;
    const int m0 = mt * BM, n0 = nt * BN;

    // ---- q = cos(2*x[:, :8] + theta) into smem (rows 0..127) ----
    if (tid < BM) {
        const float* xr = x + (size_t)(m0 + tid) * E_DIM;
        float4 x0 = ((const float4*)xr)[0];
        float4 x1 = ((const float4*)xr)[1];
        float* qd = (float*)(gb + SQ) + tid * 8;
        qd[0] = cosf(2.0f * x0.x + __ldg(theta + 0));
        qd[1] = cosf(2.0f * x0.y + __ldg(theta + 1));
        qd[2] = cosf(2.0f * x0.z + __ldg(theta + 2));
        qd[3] = cosf(2.0f * x0.w + __ldg(theta + 3));
        qd[4] = cosf(2.0f * x1.x + __ldg(theta + 4));
        qd[5] = cosf(2.0f * x1.y + __ldg(theta + 5));
        qd[6] = cosf(2.0f * x1.z + __ldg(theta + 6));
        qd[7] = cosf(2.0f * x1.w + __ldg(theta + 7));
    }
    __syncthreads();

    // ---- producer constants ----
    // A: kq warp-uniform k-group; thread handles rows rp and rp+64
    const int kq = warp & 3;
    const int rp = ((warp >> 2) << 5) + lane;       // 0..63
    const int r1 = rp + 64;
    float4 qa0, qa1, qb0, qb1;
    {
        const float* qp = (const float*)(gb + SQ);
        qa0 = ((const float4*)(qp + rp * 8))[0];
        qa1 = ((const float4*)(qp + rp * 8))[1];
        qb0 = ((const float4*)(qp + r1 * 8))[0];
        qb1 = ((const float4*)(qp + r1 * 8))[1];
    }
    const uint32_t aAddr0 = sbase + SA0 + rp * 64 + (((uint32_t)kq ^ ((rp >> 1) & 3)) << 4);
    const uint32_t aAddr1 = sbase + SA0 + r1 * 64 + (((uint32_t)kq ^ ((r1 >> 1) & 3)) << 4);
    // B: thread covers rows bnr and bnr+64, 16B column bc (cp.async, no regs)
    const int bnr = tid >> 2, bc = tid & 3;
    const uint32_t bDst0 = sbase + SB0 + bnr * 64 + (((uint32_t)bc ^ ((bnr >> 1) & 3)) << 4);
    const uint32_t bDst1 = sbase + SB0 + (bnr + 64) * 64 +
                           (((uint32_t)bc ^ (((bnr + 64) >> 1) & 3)) << 4);
    const uint4* w2p0 = g_W2h + (size_t)(n0 + bnr) * 256 + bc;
    const uint4* w2p1 = g_W2h + (size_t)(n0 + bnr + 64) * 256 + bc;

    // ---- consumer constants ----
    const int t8 = lane >> 3, r8 = lane & 7;
    const int aCrow = wm * 64 + (t8 & 1) * 8 + r8;
    const uint32_t aCs = (aCrow >> 1) & 3;
    const uint32_t aCbase = sbase + SA0 + aCrow * 64;
    const int aCk = t8 >> 1;
    const int bCrow = wn * 32 + (t8 >> 1) * 8 + r8;
    const uint32_t bCs = (bCrow >> 1) & 3;
    const uint32_t bCbase = sbase + SB0 + bCrow * 64;
    const int bCk = t8 & 1;

    float acc[4][4][4];
    #pragma unroll
    for (int i = 0; i < 4; ++i)
        #pragma unroll
        for (int j = 0; j < 4; ++j)
            #pragma unroll
            for (int e = 0; e < 4; ++e) acc[i][j][e] = 0.0f;

    // ---- prologue: chunk 0 into buffer 0 ----
    {
        cpasync16(bDst0, w2p0);
        cpasync16(bDst1, w2p1);
        asm volatile("cp.async.commit_group;" ::: "memory");

        const float* wrow = W1 + (size_t)(kq * 8) * 8;
        uint32_t pk0[4], pk1[4];
        #pragma unroll
        for (int jp = 0; jp < 4; ++jp) {
            float s0a, s1a, s0b, s1b;
            {
                float4 wa = ((const float4*)(wrow + (jp * 2) * 8))[0];
                float4 wb = ((const float4*)(wrow + (jp * 2) * 8))[1];
                s0a = fmaxf(dot8(qa0, qa1, wa, wb), 0.0f);
                s1a = fmaxf(dot8(qb0, qb1, wa, wb), 0.0f);
            }
            {
                float4 wa = ((const float4*)(wrow + (jp * 2 + 1) * 8))[0];
                float4 wb = ((const float4*)(wrow + (jp * 2 + 1) * 8))[1];
                s0b = fmaxf(dot8(qa0, qa1, wa, wb), 0.0f);
                s1b = fmaxf(dot8(qb0, qb1, wa, wb), 0.0f);
            }
            __half2 h0 = __floats2half2_rn(s0a, s0b);
            __half2 h1 = __floats2half2_rn(s1a, s1b);
            pk0[jp] = *(uint32_t*)&h0;
            pk1[jp] = *(uint32_t*)&h1;
        }
        sts128(aAddr0, pk0[0], pk0[1], pk0[2], pk0[3]);
        sts128(aAddr1, pk1[0], pk1[1], pk1[2], pk1[3]);
        asm volatile("cp.async.wait_group 0;" ::: "memory");
    }
    __syncthreads();

    for (int it = 0; it < K_ITERS; ++it) {
        const int b = it & 1, nb = b ^ 1;
        const bool dp = (it + 1 < K_ITERS);
        const int kkn = (it + 1) * BK;

        // ---- kick off next B chunk (async, no registers) ----
        if (dp) {
            const uint32_t o = (uint32_t)nb * SBB;
            cpasync16(bDst0 + o, w2p0 + (kkn >> 3));
            cpasync16(bDst1 + o, w2p1 + (kkn >> 3));
            asm volatile("cp.async.commit_group;" ::: "memory");
        }

        // ---- consume buffer b ----
        const uint32_t aoff = (uint32_t)b * SAB;
        const uint32_t boff = (uint32_t)b * SBB;
        #pragma unroll
        for (int ks = 0; ks < 2; ++ks) {
            uint32_t a[4][4];
            #pragma unroll
            for (int im = 0; im < 4; ++im)
                ldsm4(a[im], aCbase + aoff + im * 1024 +
                             ((((uint32_t)(ks * 2 + aCk)) ^ aCs) << 4));
            uint32_t bb[2][4];
            #pragma unroll
            for (int jp = 0; jp < 2; ++jp)
                ldsm4(bb[jp], bCbase + boff + jp * 1024 +
                              ((((uint32_t)(ks * 2 + bCk)) ^ bCs) << 4));
            #pragma unroll
            for (int im = 0; im < 4; ++im)
                #pragma unroll
                for (int jn = 0; jn < 4; ++jn)
                    mma_f16(acc[im][jn], a[im],
                            bb[jn >> 1][(jn & 1) * 2], bb[jn >> 1][(jn & 1) * 2 + 1]);
        }

        // ---- produce A chunk it+1 into buffer nb ----
        if (dp) {
            const float* wrow = W1 + (size_t)(kkn + kq * 8) * 8;
            uint32_t pk0[4], pk1[4];
            #pragma unroll
            for (int jp = 0; jp < 4; ++jp) {
                float s0a, s1a, s0b, s1b;
                {
                    float4 wa = ((const float4*)(wrow + (jp * 2) * 8))[0];
                    float4 wb = ((const float4*)(wrow + (jp * 2) * 8))[1];
                    s0a = fmaxf(dot8(qa0, qa1, wa, wb), 0.0f);
                    s1a = fmaxf(dot8(qb0, qb1, wa, wb), 0.0f);
                }
                {
                    float4 wa = ((const float4*)(wrow + (jp * 2 + 1) * 8))[0];
                    float4 wb = ((const float4*)(wrow + (jp * 2 + 1) * 8))[1];
                    s0b = fmaxf(dot8(qa0, qa1, wa, wb), 0.0f);
                    s1b = fmaxf(dot8(qb0, qb1, wa, wb), 0.0f);
                }
                __half2 h0 = __floats2half2_rn(s0a, s0b);
                __half2 h1 = __floats2half2_rn(s1a, s1b);
                pk0[jp] = *(uint32_t*)&h0;
                pk1[jp] = *(uint32_t*)&h1;
            }
            sts128(aAddr0 + (uint32_t)nb * SAB, pk0[0], pk0[1], pk0[2], pk0[3]);
            sts128(aAddr1 + (uint32_t)nb * SAB, pk1[0], pk1[1], pk1[2], pk1[3]);
            asm volatile("cp.async.wait_group 0;" ::: "memory");
        }
        __syncthreads();
    }

    // ---- epilogue: acc -> out ----
    const int g = lane >> 2, tq = lane & 3;
    #pragma unroll
    for (int im = 0; im < 4; ++im) {
        const int row0 = m0 + wm * 64 + im * 16 + g;
        #pragma unroll
        for (int jn = 0; jn < 4; ++jn) {
            const int col = n0 + wn * 32 + jn * 8 + tq * 2;
            *(float2*)(out + (size_t)row0 * E_DIM + col) =
                make_float2(acc[im][jn][0], acc[im][jn][1]);
            *(float2*)(out + (size_t)(row0 + 8) * E_DIM + col) =
                make_float2(acc[im][jn][2], acc[im][jn][3]);
        }
    }
}

extern "C" void kernel_launch(void* const* d_in, const int* in_sizes, int n_in,
                              void* d_out, int out_size) {
    const float* x     = (const float*)d_in[0];
    const float* theta = (const float*)d_in[1];
    const float* W1    = (const float*)d_in[2];
    const float* W2    = (const float*)d_in[3];
    float* out = (float*)d_out;

    cvt_w2_kernel<<<(E_DIM * F_DIM / 4) / 256, 256>>>(W2);

    cudaFuncSetAttribute(ffq_kernel, cudaFuncAttributeMaxDynamicSharedMemorySize, SMEM_BYTES);
    dim3 grid((M_TOTAL / BM) * (E_DIM / BN));  // 256 * 4 = 1024 CTAs
    ffq_kernel<<<grid, THREADS, SMEM_BYTES>>>(x, theta, W1, out);
}

// round 8
// speedup vs baseline: 1.0543x; 1.0543x over previous
#include <cuda_runtime.h>
#include <cuda_fp16.h>
#include <math.h>
#include <stdint.h>

#define M_TOTAL 32768
#define E_DIM   512
#define F_DIM   2048

#define BM 128
#define BN 256
#define BK 64
#define THREADS 512
#define K_ITERS 32

// smem offsets (relative to 1024-aligned base)
#define SQ   0           // q fp32 [128][8] = 4096
#define SA0  4096        // A (H fp16) [128 rows][128B] dbl: 2 x 16384
#define SAB  16384
#define SB0  36864       // B (W2 fp16) [256 rows][128B] dbl: 2 x 32768
#define SBB  32768
#define SMEM_BYTES (102400 + 1024)

// fp16 copy of W2 (E x F), row-major [n][k], uint4 = 8 halves
__device__ uint4 g_W2h[E_DIM * F_DIM / 8];

__global__ void cvt_w2_kernel(const float* __restrict__ W2) {
    int i = blockIdx.x * 256 + threadIdx.x;
    float4 v = ((const float4*)W2)[i];
    __half2* o = (__half2*)g_W2h;
    o[2 * i]     = __floats2half2_rn(v.x, v.y);
    o[2 * i + 1] = __floats2half2_rn(v.z, v.w);
}

static __device__ __forceinline__ uint32_t cvta_smem(const void* p) {
    uint32_t a;
    asm("{ .reg .u64 t; cvta.to.shared.u64 t, %1; cvt.u32.u64 %0, t; }" : "=r"(a) : "l"(p));
    return a;
}

static __device__ __forceinline__ void sts128(uint32_t addr, uint32_t r0, uint32_t r1,
                                              uint32_t r2, uint32_t r3) {
    asm volatile("st.shared.v4.b32 [%0], {%1,%2,%3,%4};"
                 :: "r"(addr), "r"(r0), "r"(r1), "r"(r2), "r"(r3) : "memory");
}

static __device__ __forceinline__ void cpasync16(uint32_t dst, const void* src) {
    asm volatile("cp.async.ca.shared.global [%0], [%1], 16;"
                 :: "r"(dst), "l"(src) : "memory");
}

static __device__ __forceinline__ void ldsm4(uint32_t* r, uint32_t a) {
    asm volatile("ldmatrix.sync.aligned.m8n8.x4.shared.b16 {%0,%1,%2,%3}, [%4];"
                 : "=r"(r[0]), "=r"(r[1]), "=r"(r[2]), "=r"(r[3]) : "r"(a));
}

static __device__ __forceinline__ void mma_f16(float* c, const uint32_t* a,
                                               uint32_t b0, uint32_t b1) {
    asm volatile(
        "mma.sync.aligned.m16n8k16.row.col.f32.f16.f16.f32 "
        "{%0,%1,%2,%3},{%4,%5,%6,%7},{%8,%9},{%0,%1,%2,%3};"
        : "+f"(c[0]), "+f"(c[1]), "+f"(c[2]), "+f"(c[3])
        : "r"(a[0]), "r"(a[1]), "r"(a[2]), "r"(a[3]), "r"(b0), "r"(b1));
}

static __device__ __forceinline__ float dot8(const float4& qa, const float4& qb,
                                             const float4& wa, const float4& wb) {
    float t = qa.x * wa.x;
    t = fmaf(qa.y, wa.y, t);
    t = fmaf(qa.z, wa.z, t);
    t = fmaf(qa.w, wa.w, t);
    t = fmaf(qb.x, wb.x, t);
    t = fmaf(qb.y, wb.y, t);
    t = fmaf(qb.z, wb.z, t);
    t = fmaf(qb.w, wb.w, t);
    return t;
}

__global__ void __launch_bounds__(THREADS, 1)
ffq_kernel(const float* __restrict__ x,
           const float* __restrict__ theta,
           const float* __restrict__ W1,
           float* __restrict__ out)
{
    extern __shared__ char dsm[];
    const uint32_t raw = cvta_smem(dsm);
    const uint32_t sbase = (raw + 1023) & ~1023u;
    char* gb = dsm + (sbase - raw);

    const int tid  = threadIdx.x;
    const int warp = tid >> 5, lane = tid & 31;
    const int wm = warp >> 2, wn = warp & 3;       // consumer: 4 x 4 grid, warp tile 32x64
    const int mt = blockIdx.x >> 1, nt = blockIdx.x & 1;
    const int m0 = mt * BM, n0 = nt * BN;

    // ---- q = cos(2*x[:, :8] + theta) into smem (rows 0..127) ----
    if (tid < BM) {
        const float* xr = x + (size_t)(m0 + tid) * E_DIM;
        float4 x0 = ((const float4*)xr)[0];
        float4 x1 = ((const float4*)xr)[1];
        float* qd = (float*)(gb + SQ) + tid * 8;
        qd[0] = cosf(2.0f * x0.x + __ldg(theta + 0));
        qd[1] = cosf(2.0f * x0.y + __ldg(theta + 1));
        qd[2] = cosf(2.0f * x0.z + __ldg(theta + 2));
        qd[3] = cosf(2.0f * x0.w + __ldg(theta + 3));
        qd[4] = cosf(2.0f * x1.x + __ldg(theta + 4));
        qd[5] = cosf(2.0f * x1.y + __ldg(theta + 5));
        qd[6] = cosf(2.0f * x1.z + __ldg(theta + 6));
        qd[7] = cosf(2.0f * x1.w + __ldg(theta + 7));
    }
    __syncthreads();

    // ---- A producer constants: kq = warp&7 (warp-uniform k-group of 8),
    //      thread covers rows rp and rp+64 ----
    const int kq = warp & 7;
    const int rp = ((warp >> 3) << 5) + lane;       // 0..63
    const int r1 = rp + 64;
    float4 qa0, qa1, qb0, qb1;
    {
        const float* qp = (const float*)(gb + SQ);
        qa0 = ((const float4*)(qp + rp * 8))[0];
        qa1 = ((const float4*)(qp + rp * 8))[1];
        qb0 = ((const float4*)(qp + r1 * 8))[0];
        qb1 = ((const float4*)(qp + r1 * 8))[1];
    }
    const uint32_t aAddr0 = sbase + SA0 + rp * 128 + (((uint32_t)(kq ^ (rp & 7))) << 4);
    const uint32_t aAddr1 = sbase + SA0 + r1 * 128 + (((uint32_t)(kq ^ (r1 & 7))) << 4);

    // ---- B producer constants: thread covers row tid>>1, four 16B cols ----
    const int bnr = tid >> 1;                       // 0..255
    const int bc0 = (tid & 1) * 4;                  // 0 or 4
    const uint32_t bRow = sbase + SB0 + bnr * 128;
    const uint4* w2p = g_W2h + (size_t)(n0 + bnr) * 256 + bc0;

    // ---- consumer constants ----
    const int t8 = lane >> 3, r8 = lane & 7;
    const int aCrow = wm * 32 + (t8 & 1) * 8 + r8;
    const uint32_t aCx = (uint32_t)(aCrow & 7);
    const uint32_t aCbase = sbase + SA0 + aCrow * 128;
    const int aCk = t8 >> 1;
    const int bCrow = wn * 64 + (t8 >> 1) * 8 + r8;
    const uint32_t bCx = (uint32_t)(bCrow & 7);
    const uint32_t bCbase = sbase + SB0 + bCrow * 128;
    const int bCk = t8 & 1;

    float acc[2][8][4];
    #pragma unroll
    for (int i = 0; i < 2; ++i)
        #pragma unroll
        for (int j = 0; j < 8; ++j)
            #pragma unroll
            for (int e = 0; e < 4; ++e) acc[i][j][e] = 0.0f;

    // ---- prologue: chunk 0 into buffer 0 ----
    {
        #pragma unroll
        for (int j = 0; j < 4; ++j) {
            int c = bc0 + j;
            cpasync16(bRow + (((uint32_t)(c ^ (bnr & 7))) << 4), w2p + j);
        }
        asm volatile("cp.async.commit_group;" ::: "memory");

        const float* wrow = W1 + (size_t)(kq * 8) * 8;
        uint32_t pk0[4], pk1[4];
        #pragma unroll
        for (int jp = 0; jp < 4; ++jp) {
            float s0a, s1a, s0b, s1b;
            {
                float4 wa = ((const float4*)(wrow + (jp * 2) * 8))[0];
                float4 wb = ((const float4*)(wrow + (jp * 2) * 8))[1];
                s0a = fmaxf(dot8(qa0, qa1, wa, wb), 0.0f);
                s1a = fmaxf(dot8(qb0, qb1, wa, wb), 0.0f);
            }
            {
                float4 wa = ((const float4*)(wrow + (jp * 2 + 1) * 8))[0];
                float4 wb = ((const float4*)(wrow + (jp * 2 + 1) * 8))[1];
                s0b = fmaxf(dot8(qa0, qa1, wa, wb), 0.0f);
                s1b = fmaxf(dot8(qb0, qb1, wa, wb), 0.0f);
            }
            __half2 h0 = __floats2half2_rn(s0a, s0b);
            __half2 h1 = __floats2half2_rn(s1a, s1b);
            pk0[jp] = *(uint32_t*)&h0;
            pk1[jp] = *(uint32_t*)&h1;
        }
        sts128(aAddr0, pk0[0], pk0[1], pk0[2], pk0[3]);
        sts128(aAddr1, pk1[0], pk1[1], pk1[2], pk1[3]);
        asm volatile("cp.async.wait_group 0;" ::: "memory");
    }
    __syncthreads();

    for (int it = 0; it < K_ITERS; ++it) {
        const int b = it & 1, nb = b ^ 1;
        const bool dp = (it + 1 < K_ITERS);
        const int kkn = (it + 1) * BK;

        // ---- kick off next B chunk (async) ----
        if (dp) {
            const uint32_t o = (uint32_t)nb * SBB;
            const uint4* src = w2p + (kkn >> 3);
            #pragma unroll
            for (int j = 0; j < 4; ++j) {
                int c = bc0 + j;
                cpasync16(bRow + o + (((uint32_t)(c ^ (bnr & 7))) << 4), src + j);
            }
            asm volatile("cp.async.commit_group;" ::: "memory");
        }

        // ---- consume buffer b (4 ks blocks of k16) ----
        const uint32_t aoff = (uint32_t)b * SAB;
        const uint32_t boff = (uint32_t)b * SBB;
        #pragma unroll
        for (int ks = 0; ks < 4; ++ks) {
            uint32_t a[2][4];
            #pragma unroll
            for (int im = 0; im < 2; ++im)
                ldsm4(a[im], aCbase + aoff + im * 2048 +
                             ((((uint32_t)(ks * 2 + aCk)) ^ aCx) << 4));
            uint32_t bb[4][4];
            #pragma unroll
            for (int jp = 0; jp < 4; ++jp)
                ldsm4(bb[jp], bCbase + boff + jp * 2048 +
                              ((((uint32_t)(ks * 2 + bCk)) ^ bCx) << 4));
            #pragma unroll
            for (int im = 0; im < 2; ++im)
                #pragma unroll
                for (int jn = 0; jn < 8; ++jn)
                    mma_f16(acc[im][jn], a[im],
                            bb[jn >> 1][(jn & 1) * 2], bb[jn >> 1][(jn & 1) * 2 + 1]);
        }

        // ---- produce A chunk it+1 into buffer nb ----
        if (dp) {
            const float* wrow = W1 + (size_t)(kkn + kq * 8) * 8;
            uint32_t pk0[4], pk1[4];
            #pragma unroll
            for (int jp = 0; jp < 4; ++jp) {
                float s0a, s1a, s0b, s1b;
                {
                    float4 wa = ((const float4*)(wrow + (jp * 2) * 8))[0];
                    float4 wb = ((const float4*)(wrow + (jp * 2) * 8))[1];
                    s0a = fmaxf(dot8(qa0, qa1, wa, wb), 0.0f);
                    s1a = fmaxf(dot8(qb0, qb1, wa, wb), 0.0f);
                }
                {
                    float4 wa = ((const float4*)(wrow + (jp * 2 + 1) * 8))[0];
                    float4 wb = ((const float4*)(wrow + (jp * 2 + 1) * 8))[1];
                    s0b = fmaxf(dot8(qa0, qa1, wa, wb), 0.0f);
                    s1b = fmaxf(dot8(qb0, qb1, wa, wb), 0.0f);
                }
                __half2 h0 = __floats2half2_rn(s0a, s0b);
                __half2 h1 = __floats2half2_rn(s1a, s1b);
                pk0[jp] = *(uint32_t*)&h0;
                pk1[jp] = *(uint32_t*)&h1;
            }
            sts128(aAddr0 + (uint32_t)nb * SAB, pk0[0], pk0[1], pk0[2], pk0[3]);
            sts128(aAddr1 + (uint32_t)nb * SAB, pk1[0], pk1[1], pk1[2], pk1[3]);
            asm volatile("cp.async.wait_group 0;" ::: "memory");
        }
        __syncthreads();
    }

    // ---- epilogue: acc -> out ----
    const int g = lane >> 2, tq = lane & 3;
    #pragma unroll
    for (int im = 0; im < 2; ++im) {
        const int row0 = m0 + wm * 32 + im * 16 + g;
        #pragma unroll
        for (int jn = 0; jn < 8; ++jn) {
            const int col = n0 + wn * 64 + jn * 8 + tq * 2;
            *(float2*)(out + (size_t)row0 * E_DIM + col) =
                make_float2(acc[im][jn][0], acc[im][jn][1]);
            *(float2*)(out + (size_t)(row0 + 8) * E_DIM + col) =
                make_float2(acc[im][jn][2], acc[im][jn][3]);
        }
    }
}

extern "C" void kernel_launch(void* const* d_in, const int* in_sizes, int n_in,
                              void* d_out, int out_size) {
    const float* x     = (const float*)d_in[0];
    const float* theta = (const float*)d_in[1];
    const float* W1    = (const float*)d_in[2];
    const float* W2    = (const float*)d_in[3];
    float* out = (float*)d_out;

    cvt_w2_kernel<<<(E_DIM * F_DIM / 4) / 256, 256>>>(W2);

    cudaFuncSetAttribute(ffq_kernel, cudaFuncAttributeMaxDynamicSharedMemorySize, SMEM_BYTES);
    dim3 grid((M_TOTAL / BM) * (E_DIM / BN));  // 256 * 2 = 512 CTAs
    ffq_kernel<<<grid, THREADS, SMEM_BYTES>>>(x, theta, W1, out);
}